// round 13
// baseline (speedup 1.0000x reference)
#include <cuda_runtime.h>
#include <math.h>

// 3D shifted-window attention, fused, conflict-free smem, 512 threads/CTA,
// packed fp32x2 FMA (FFMA2) in all hot loops.
// One CTA per 4x4x4 window; 4096 windows.

#define C_DIM    192
#define THREADS  512
#define NTOK     64
#define NWIN     4096
#define HEADS    6
#define HDIM     32
#define QKV_OUT  576

typedef unsigned long long u64;

// packed f32x2 helpers (sm_100+): d = a*b + d elementwise on 2 packed floats
__device__ __forceinline__ void ffma2(u64& d, u64 a, u64 b) {
    asm("fma.rn.f32x2 %0, %1, %2, %0;" : "+l"(d) : "l"(a), "l"(b));
}
__device__ __forceinline__ u64 dup2(float w) {
    u64 r; asm("mov.b64 %0, {%1, %1};" : "=l"(r) : "f"(w)); return r;
}
__device__ __forceinline__ u64 mul2(u64 a, u64 b) {
    u64 r; asm("mul.rn.f32x2 %0, %1, %2;" : "=l"(r) : "l"(a), "l"(b)); return r;
}
__device__ __forceinline__ u64 add2(u64 a, u64 b) {
    u64 r; asm("add.rn.f32x2 %0, %1, %2;" : "=l"(r) : "l"(a), "l"(b)); return r;
}

// pre-transposed weights [c][o]
__device__ float g_wt_qkv[C_DIM * QKV_OUT];   // stride 576
__device__ float g_wt_proj[C_DIM * C_DIM];    // stride 192

// smem layout (floats)
#define XS_OFF   0                    // xs [c][t]     192*64 = 12288
#define QK_OFF   12288                // qkv [o][t]    576*64 = 36864 ; later proj-out
#define ST_OFF   49152                // sT [j][i]      64*64 =  4096
#define WT_OFF   53248                // W tile [32][128]     =  4096
#define RED_OFF  57344                // partials [8][64]     =   512
#define SMEM_FLOATS 57856
#define SMEM_BYTES  (SMEM_FLOATS * 4 + 64 * 4)   // + goff[64]

__global__ void transpose_weights(const float* __restrict__ qkv_w,
                                  const float* __restrict__ proj_w)
{
    int i = blockIdx.x * blockDim.x + threadIdx.x;
    if (i < C_DIM * QKV_OUT) {
        int c = i / QKV_OUT, o = i % QKV_OUT;
        g_wt_qkv[i] = qkv_w[o * C_DIM + c];
    } else {
        int j = i - C_DIM * QKV_OUT;
        if (j < C_DIM * C_DIM) {
            int c = j / C_DIM, o = j % C_DIM;
            g_wt_proj[j] = proj_w[o * C_DIM + c];
        }
    }
}

// 128-wide output tile GEMM: dst[o][t], K=192, micro 4o x 4t (acc as 4x2 f32x2)
__device__ __forceinline__ void gemm_tile128(
    const float* __restrict__ gw, int gw_stride, int o0,
    const float* __restrict__ src, float* wt,
    const float* __restrict__ bias, float* dst, int tid)
{
    const int o_thr = tid >> 4;   // 0..31
    const int t_thr = tid & 15;
    u64 acc[4][2] = {};
    for (int ct = 0; ct < 6; ++ct) {
        const int c0 = ct * 32;
        __syncthreads();
        #pragma unroll
        for (int p = 0; p < 2; ++p) {
            int s = tid + p * THREADS;              // 0..1023
            int cr = s >> 5, o4 = (s & 31) * 4;
            *reinterpret_cast<float4*>(&wt[cr * 128 + o4]) =
                *reinterpret_cast<const float4*>(&gw[(size_t)(c0 + cr) * gw_stride + o0 + o4]);
        }
        __syncthreads();
        #pragma unroll 8
        for (int k = 0; k < 32; ++k) {
            ulonglong2 av = *reinterpret_cast<const ulonglong2*>(&src[(c0 + k) * 64 + t_thr * 4]);
            float4 wv = *reinterpret_cast<const float4*>(&wt[k * 128 + o_thr * 4]);
            u64 w0 = dup2(wv.x), w1 = dup2(wv.y), w2 = dup2(wv.z), w3 = dup2(wv.w);
            ffma2(acc[0][0], w0, av.x); ffma2(acc[0][1], w0, av.y);
            ffma2(acc[1][0], w1, av.x); ffma2(acc[1][1], w1, av.y);
            ffma2(acc[2][0], w2, av.x); ffma2(acc[2][1], w2, av.y);
            ffma2(acc[3][0], w3, av.x); ffma2(acc[3][1], w3, av.y);
        }
    }
    float4 bv = __ldg(reinterpret_cast<const float4*>(bias + o0 + o_thr * 4));
    u64 bb[4] = {dup2(bv.x), dup2(bv.y), dup2(bv.z), dup2(bv.w)};
    #pragma unroll
    for (int oi = 0; oi < 4; ++oi) {
        ulonglong2 ov;
        ov.x = add2(acc[oi][0], bb[oi]);
        ov.y = add2(acc[oi][1], bb[oi]);
        *reinterpret_cast<ulonglong2*>(&dst[(o0 + o_thr * 4 + oi) * 64 + t_thr * 4]) = ov;
    }
}

// 64-wide output tail tile GEMM (micro 2o x 4t, acc as 2x2 f32x2)
__device__ __forceinline__ void gemm_tile64(
    const float* __restrict__ gw, int gw_stride, int o0,
    const float* __restrict__ src, float* wt,
    const float* __restrict__ bias, float* dst, int tid)
{
    const int o_thr = tid >> 4;   // 0..31, *2
    const int t_thr = tid & 15;
    u64 acc[2][2] = {};
    for (int ct = 0; ct < 6; ++ct) {
        const int c0 = ct * 32;
        __syncthreads();
        {
            int cr = tid >> 4, o4 = (tid & 15) * 4;
            *reinterpret_cast<float4*>(&wt[cr * 64 + o4]) =
                *reinterpret_cast<const float4*>(&gw[(size_t)(c0 + cr) * gw_stride + o0 + o4]);
        }
        __syncthreads();
        #pragma unroll 8
        for (int k = 0; k < 32; ++k) {
            ulonglong2 av = *reinterpret_cast<const ulonglong2*>(&src[(c0 + k) * 64 + t_thr * 4]);
            float2 wv = *reinterpret_cast<const float2*>(&wt[k * 64 + o_thr * 2]);
            u64 w0 = dup2(wv.x), w1 = dup2(wv.y);
            ffma2(acc[0][0], w0, av.x); ffma2(acc[0][1], w0, av.y);
            ffma2(acc[1][0], w1, av.x); ffma2(acc[1][1], w1, av.y);
        }
    }
    float2 bv = __ldg(reinterpret_cast<const float2*>(bias + o0 + o_thr * 2));
    u64 bb[2] = {dup2(bv.x), dup2(bv.y)};
    #pragma unroll
    for (int oi = 0; oi < 2; ++oi) {
        ulonglong2 ov;
        ov.x = add2(acc[oi][0], bb[oi]);
        ov.y = add2(acc[oi][1], bb[oi]);
        *reinterpret_cast<ulonglong2*>(&dst[(o0 + o_thr * 2 + oi) * 64 + t_thr * 4]) = ov;
    }
}

__global__ __launch_bounds__(THREADS, 1)
void win_attn_kernel(const float* __restrict__ x,
                     const float* __restrict__ qkv_b,
                     const float* __restrict__ proj_b,
                     float* __restrict__ out)
{
    extern __shared__ float sm[];
    float* xs   = sm + XS_OFF;
    float* qkvs = sm + QK_OFF;
    float* st   = sm + ST_OFF;
    float* wt   = sm + WT_OFF;
    float* red  = sm + RED_OFF;
    int*   goff = (int*)(sm + SMEM_FLOATS);

    const int tid = threadIdx.x;
    const int w   = blockIdx.x;
    const int wx  = w >> 8, wy = (w >> 4) & 15, wz = w & 15;

    if (tid < NTOK) {
        int tx = tid >> 4, ty = (tid >> 2) & 3, tz = tid & 3;
        int gx = (wx * 4 + tx + 2) & 63;
        int gy = (wy * 4 + ty + 2) & 63;
        int gz = (wz * 4 + tz + 2) & 63;
        goff[tid] = (gx << 12) + (gy << 6) + gz;
    }
    __syncthreads();

    // gather x tile: xs[c*64 + t]
    #pragma unroll 4
    for (int idx = tid; idx < C_DIM * NTOK; idx += THREADS) {
        int c = idx >> 6, t = idx & 63;
        xs[idx] = __ldg(x + ((size_t)c << 18) + goff[t]);
    }
    // (first __syncthreads inside gemm_tile128 covers the gather)

    // ================= QKV GEMM: qkvs[o][t], o in [0,576) ====================
    #pragma unroll 1
    for (int ot = 0; ot < 4; ++ot)
        gemm_tile128(g_wt_qkv, QKV_OUT, ot * 128, xs, wt, qkv_b, qkvs, tid);
    gemm_tile64(g_wt_qkv, QKV_OUT, 512, xs, wt, qkv_b, qkvs, tid);

    // ================= attention per head ====================================
    const float scale = 0.17677669529663688f;  // 1/sqrt(32)
    #pragma unroll 1
    for (int h = 0; h < HEADS; ++h) {
        const int qo = h * HDIM, ko = C_DIM + h * HDIM, vo = 2 * C_DIM + h * HDIM;
        __syncthreads();

        // ---- scores: sT[j][i] = (q_i . k_j) * scale   (micro 4i x 2j, f32x2)
        {
            const int i_thr = tid & 15, j_thr = tid >> 4;  // j_thr 0..31 (*2)
            u64 acc[2][2] = {};   // [jj][i-pair]
            #pragma unroll 8
            for (int d = 0; d < HDIM; ++d) {
                ulonglong2 qp = *reinterpret_cast<const ulonglong2*>(&qkvs[(qo + d) * 64 + i_thr * 4]);
                float2 kv = *reinterpret_cast<const float2*>(&qkvs[(ko + d) * 64 + j_thr * 2]);
                u64 k0 = dup2(kv.x), k1 = dup2(kv.y);
                ffma2(acc[0][0], k0, qp.x); ffma2(acc[0][1], k0, qp.y);
                ffma2(acc[1][0], k1, qp.x); ffma2(acc[1][1], k1, qp.y);
            }
            u64 sc = dup2(scale);
            #pragma unroll
            for (int jj = 0; jj < 2; ++jj) {
                ulonglong2 sv;
                sv.x = mul2(acc[jj][0], sc);
                sv.y = mul2(acc[jj][1], sc);
                *reinterpret_cast<ulonglong2*>(&st[(j_thr * 2 + jj) * 64 + i_thr * 4]) = sv;
            }
        }
        __syncthreads();

        // ---- softmax over columns of sT: 8 partials per column
        const int col = tid & 63, sub = tid >> 6;   // sub 0..7, 8 rows each
        {
            float part = -1e30f;
            #pragma unroll
            for (int jj = 0; jj < 8; ++jj)
                part = fmaxf(part, st[(sub * 8 + jj) * 64 + col]);
            red[sub * 64 + col] = part;
        }
        __syncthreads();
        {
            float m = red[col];
            #pragma unroll
            for (int r = 1; r < 8; ++r) m = fmaxf(m, red[r * 64 + col]);
            __syncthreads();   // all partial-max reads done before red reused
            float sum = 0.f;
            #pragma unroll
            for (int jj = 0; jj < 8; ++jj) {
                int a = (sub * 8 + jj) * 64 + col;
                float e = __expf(st[a] - m);
                st[a] = e;
                sum += e;
            }
            red[sub * 64 + col] = sum;
        }
        __syncthreads();
        // combine partial sums -> red[0..63] = 1/rowsum
        if (tid < NTOK) {
            float tot = red[tid];
            #pragma unroll
            for (int r = 1; r < 8; ++r) tot += red[r * 64 + tid];
            red[tid] = __frcp_rn(tot);
        }
        __syncthreads();

        // ---- AV: xs[qo+d][i] = (sum_j e[j][i] * v[d][j]) * inv(i)   (f32x2)
        {
            const int i_thr = tid & 15, d_thr = tid >> 4;   // d 0..31
            u64 acc[2] = {};
            #pragma unroll 4
            for (int j0 = 0; j0 < 64; j0 += 4) {
                float4 vv = *reinterpret_cast<const float4*>(&qkvs[(vo + d_thr) * 64 + j0]);
                u64 v0 = dup2(vv.x), v1 = dup2(vv.y), v2 = dup2(vv.z), v3 = dup2(vv.w);
                ulonglong2 s0 = *reinterpret_cast<const ulonglong2*>(&st[(j0 + 0) * 64 + i_thr * 4]);
                ulonglong2 s1 = *reinterpret_cast<const ulonglong2*>(&st[(j0 + 1) * 64 + i_thr * 4]);
                ulonglong2 s2 = *reinterpret_cast<const ulonglong2*>(&st[(j0 + 2) * 64 + i_thr * 4]);
                ulonglong2 s3 = *reinterpret_cast<const ulonglong2*>(&st[(j0 + 3) * 64 + i_thr * 4]);
                ffma2(acc[0], v0, s0.x); ffma2(acc[1], v0, s0.y);
                ffma2(acc[0], v1, s1.x); ffma2(acc[1], v1, s1.y);
                ffma2(acc[0], v2, s2.x); ffma2(acc[1], v2, s2.y);
                ffma2(acc[0], v3, s3.x); ffma2(acc[1], v3, s3.y);
            }
            ulonglong2 ip = *reinterpret_cast<const ulonglong2*>(&red[i_thr * 4]);
            ulonglong2 ov;
            ov.x = mul2(acc[0], ip.x);
            ov.y = mul2(acc[1], ip.y);
            *reinterpret_cast<ulonglong2*>(&xs[(qo + d_thr) * 64 + i_thr * 4]) = ov;
        }
    }

    // ================= proj GEMM: po[o][t] into qkvs region ===================
    gemm_tile128(g_wt_proj, C_DIM, 0,   xs, wt, proj_b, qkvs, tid);
    gemm_tile64 (g_wt_proj, C_DIM, 128, xs, wt, proj_b, qkvs, tid);
    __syncthreads();

    // ================= scatter ===============================================
    #pragma unroll 4
    for (int idx = tid; idx < C_DIM * NTOK; idx += THREADS) {
        int c = idx >> 6, t = idx & 63;
        out[((size_t)c << 18) + goff[t]] = qkvs[idx];
    }
}

extern "C" void kernel_launch(void* const* d_in, const int* in_sizes, int n_in,
                              void* d_out, int out_size)
{
    const float* x      = (const float*)d_in[0];
    const float* qkv_w  = (const float*)d_in[1];
    const float* qkv_b  = (const float*)d_in[2];
    const float* proj_w = (const float*)d_in[3];
    const float* proj_b = (const float*)d_in[4];
    float* out = (float*)d_out;

    int n_t = C_DIM * QKV_OUT + C_DIM * C_DIM;
    transpose_weights<<<(n_t + 255) / 256, 256>>>(qkv_w, proj_w);

    cudaFuncSetAttribute(win_attn_kernel,
                         cudaFuncAttributeMaxDynamicSharedMemorySize, SMEM_BYTES);
    win_attn_kernel<<<NWIN, THREADS, SMEM_BYTES>>>(x, qkv_b, proj_b, out);
}

// round 17
// speedup vs baseline: 1.8281x; 1.8281x over previous
#include <cuda_runtime.h>

// 3D shifted-window attention: mma.sync tf32 (base-PTX HMMA) GEMMs + SIMT attention.
// One CTA per 4x4x4 window; 4096 CTAs; 512 threads.

#define C_DIM   192
#define THREADS 512
#define NWIN    4096
#define HEADS   6

// smem layout (float offsets)
#define XS_OFF   0        // x / attn-out tile [t][c], stride 196 (12544 floats)
#define QK_OFF   12544    // qkv [o][t] stride 68 (576*68=39168); later proj-out
#define SC_OFF   51712    // scores [j][i] stride 64 (4096)
#define RED_OFF  55808    // softmax partials 8x64 (512)
#define GOFF_OFF 56320    // 64 ints
#define SMEM_FLOATS 56384
#define SMEM_BYTES  (SMEM_FLOATS * 4)   // 225536

#define XST 196   // xs row stride (t-major)
#define QKT 68    // qkvs row stride (o-major)

// A-fragment arrays (fragment-ordered, tf32 bits): [mt][ks][lane] -> uint4
__device__ uint4 g_wqf[36 * 24 * 32];   // qkv  W: 576x192
__device__ uint4 g_wpf[12 * 24 * 32];   // proj W: 192x192

__device__ __forceinline__ float to_tf32(float x) {
    float r; asm("cvt.rna.tf32.f32 %0, %1;" : "=f"(r) : "f"(x)); return r;
}
__device__ __forceinline__ unsigned tf32_bits(float x) {
    return __float_as_uint(to_tf32(x));
}

__device__ __forceinline__ void mma_m16n8k8(float* d, uint4 a, unsigned b0, unsigned b1) {
    asm("mma.sync.aligned.m16n8k8.row.col.f32.tf32.tf32.f32 "
        "{%0,%1,%2,%3}, {%4,%5,%6,%7}, {%8,%9}, {%0,%1,%2,%3};"
        : "+f"(d[0]), "+f"(d[1]), "+f"(d[2]), "+f"(d[3])
        : "r"(a.x), "r"(a.y), "r"(a.z), "r"(a.w), "r"(b0), "r"(b1));
}

// ---------- prep: weights -> per-lane fragment order, tf32 ----------
__global__ void prep_frags(const float* __restrict__ qkv_w,
                           const float* __restrict__ proj_w)
{
    int i = blockIdx.x * blockDim.x + threadIdx.x;
    const int NQ = 36 * 24 * 32;
    const int NP = 12 * 24 * 32;
    if (i < NQ) {
        int lane = i & 31, rest = i >> 5;
        int ks = rest % 24, mt = rest / 24;
        int g = lane >> 2, tg = lane & 3;
        int o = mt * 16 + g, c = ks * 8 + tg;
        uint4 v;
        v.x = tf32_bits(qkv_w[o * C_DIM + c]);
        v.y = tf32_bits(qkv_w[(o + 8) * C_DIM + c]);
        v.z = tf32_bits(qkv_w[o * C_DIM + c + 4]);
        v.w = tf32_bits(qkv_w[(o + 8) * C_DIM + c + 4]);
        g_wqf[i] = v;
    } else if (i < NQ + NP) {
        int j = i - NQ;
        int lane = j & 31, rest = j >> 5;
        int ks = rest % 24, mt = rest / 24;
        int g = lane >> 2, tg = lane & 3;
        int o = mt * 16 + g, c = ks * 8 + tg;
        uint4 v;
        v.x = tf32_bits(proj_w[o * C_DIM + c]);
        v.y = tf32_bits(proj_w[(o + 8) * C_DIM + c]);
        v.z = tf32_bits(proj_w[o * C_DIM + c + 4]);
        v.w = tf32_bits(proj_w[(o + 8) * C_DIM + c + 4]);
        g_wpf[j] = v;
    }
}

// ---------- GEMM chunks: D[o][t] = W[o][c] @ xs_T, K=192 ----------
// 128-wide o-chunk: 8 mt x 8 nt tiles, warp-tile 2mt x 2nt
__device__ __forceinline__ void gemm_chunk128(
    const uint4* __restrict__ frag, int mtg0,
    const float* __restrict__ xs, const float* __restrict__ bias,
    float* __restrict__ dst, int o0, int warp, int lane)
{
    const int g = lane >> 2, tg = lane & 3;
    const int mt0 = (warp >> 2) * 2;
    const int nt0 = (warp & 3) * 2;
    float acc[2][2][4] = {};
    #pragma unroll 4
    for (int ks = 0; ks < 24; ++ks) {
        uint4 a0 = frag[((mtg0 + mt0) * 24 + ks) * 32 + lane];
        uint4 a1 = frag[((mtg0 + mt0 + 1) * 24 + ks) * 32 + lane];
        unsigned b[2][2];
        #pragma unroll
        for (int n = 0; n < 2; ++n) {
            int t = (nt0 + n) * 8 + g;
            int c = ks * 8 + tg;
            b[n][0] = __float_as_uint(xs[t * XST + c]);
            b[n][1] = __float_as_uint(xs[t * XST + c + 4]);
        }
        mma_m16n8k8(acc[0][0], a0, b[0][0], b[0][1]);
        mma_m16n8k8(acc[0][1], a0, b[1][0], b[1][1]);
        mma_m16n8k8(acc[1][0], a1, b[0][0], b[0][1]);
        mma_m16n8k8(acc[1][1], a1, b[1][0], b[1][1]);
    }
    #pragma unroll
    for (int m = 0; m < 2; ++m) {
        int ob = o0 + (mt0 + m) * 16;
        float blo = bias ? __ldg(bias + ob + g)     : 0.f;
        float bhi = bias ? __ldg(bias + ob + g + 8) : 0.f;
        #pragma unroll
        for (int n = 0; n < 2; ++n) {
            int tb = (nt0 + n) * 8 + 2 * tg;
            *(float2*)&dst[(ob + g) * QKT + tb] =
                make_float2(acc[m][n][0] + blo, acc[m][n][1] + blo);
            *(float2*)&dst[(ob + g + 8) * QKT + tb] =
                make_float2(acc[m][n][2] + bhi, acc[m][n][3] + bhi);
        }
    }
}

// 64-wide o-chunk: 4 mt x 8 nt, warp-tile 1mt x 2nt
__device__ __forceinline__ void gemm_chunk64(
    const uint4* __restrict__ frag, int mtg0,
    const float* __restrict__ xs, const float* __restrict__ bias,
    float* __restrict__ dst, int o0, int warp, int lane)
{
    const int g = lane >> 2, tg = lane & 3;
    const int mt = warp >> 2;
    const int nt0 = (warp & 3) * 2;
    float acc[2][4] = {};
    #pragma unroll 4
    for (int ks = 0; ks < 24; ++ks) {
        uint4 a0 = frag[((mtg0 + mt) * 24 + ks) * 32 + lane];
        unsigned b[2][2];
        #pragma unroll
        for (int n = 0; n < 2; ++n) {
            int t = (nt0 + n) * 8 + g;
            int c = ks * 8 + tg;
            b[n][0] = __float_as_uint(xs[t * XST + c]);
            b[n][1] = __float_as_uint(xs[t * XST + c + 4]);
        }
        mma_m16n8k8(acc[0], a0, b[0][0], b[0][1]);
        mma_m16n8k8(acc[1], a0, b[1][0], b[1][1]);
    }
    int ob = o0 + mt * 16;
    float blo = bias ? __ldg(bias + ob + g)     : 0.f;
    float bhi = bias ? __ldg(bias + ob + g + 8) : 0.f;
    #pragma unroll
    for (int n = 0; n < 2; ++n) {
        int tb = (nt0 + n) * 8 + 2 * tg;
        *(float2*)&dst[(ob + g) * QKT + tb] =
            make_float2(acc[n][0] + blo, acc[n][1] + blo);
        *(float2*)&dst[(ob + g + 8) * QKT + tb] =
            make_float2(acc[n][2] + bhi, acc[n][3] + bhi);
    }
}

// ---------- main kernel ----------
__global__ __launch_bounds__(THREADS, 1)
void win_attn_mma(const float* __restrict__ x,
                  const float* __restrict__ qkv_b,
                  const float* __restrict__ proj_b,
                  float* __restrict__ out)
{
    extern __shared__ float sm[];
    float* xs   = sm + XS_OFF;    // [t][c] stride 196 (tf32 values)
    float* qkvs = sm + QK_OFF;    // [o][t] stride 68
    float* sc   = sm + SC_OFF;    // [j][i] stride 64
    float* red  = sm + RED_OFF;
    int*   goff = (int*)(sm + GOFF_OFF);

    const int tid  = threadIdx.x;
    const int warp = tid >> 5;
    const int lane = tid & 31;
    const int w    = blockIdx.x;
    const int wx = w >> 8, wy = (w >> 4) & 15, wz = w & 15;

    if (tid < 64) {
        int tx = tid >> 4, ty = (tid >> 2) & 3, tz = tid & 3;
        int gx = (wx * 4 + tx + 2) & 63;
        int gy = (wy * 4 + ty + 2) & 63;
        int gz = (wz * 4 + tz + 2) & 63;
        goff[tid] = (gx << 12) + (gy << 6) + gz;
    }
    __syncthreads();

    // gather x -> xs[t][c] (tf32)
    #pragma unroll 4
    for (int idx = tid; idx < C_DIM * 64; idx += THREADS) {
        int c = idx >> 6, t = idx & 63;
        xs[t * XST + c] = to_tf32(__ldg(x + ((size_t)c << 18) + goff[t]));
    }
    __syncthreads();

    // ================= QKV GEMM (tensor): qkvs[o][t], o in [0,576) ==========
    const uint4* wqf = g_wqf;
    gemm_chunk128(wqf, 0,  xs, qkv_b, qkvs, 0,   warp, lane);
    gemm_chunk128(wqf, 8,  xs, qkv_b, qkvs, 128, warp, lane);
    gemm_chunk128(wqf, 16, xs, qkv_b, qkvs, 256, warp, lane);
    gemm_chunk128(wqf, 24, xs, qkv_b, qkvs, 384, warp, lane);
    gemm_chunk64 (wqf, 32, xs, qkv_b, qkvs, 512, warp, lane);
    __syncthreads();

    // ================= attention per head (SIMT) ============================
    const float scale = 0.17677669529663688f;  // 1/sqrt(32)
    #pragma unroll 1
    for (int h = 0; h < HEADS; ++h) {
        const int qo = h * 32, ko = C_DIM + h * 32, vo = 2 * C_DIM + h * 32;

        // ---- scores: sc[j][i] = (q_i . k_j) * scale  (4i x 2j micro)
        {
            const int i_thr = tid & 15, j_thr = tid >> 4;   // j_thr 0..31 (*2)
            float acc[2][4] = {};
            #pragma unroll 8
            for (int d = 0; d < 32; ++d) {
                float4 qv = *(const float4*)&qkvs[(qo + d) * QKT + i_thr * 4];
                float2 kv = *(const float2*)&qkvs[(ko + d) * QKT + j_thr * 2];
                float q4[4] = {qv.x, qv.y, qv.z, qv.w};
                #pragma unroll
                for (int ii = 0; ii < 4; ++ii) {
                    acc[0][ii] = fmaf(kv.x, q4[ii], acc[0][ii]);
                    acc[1][ii] = fmaf(kv.y, q4[ii], acc[1][ii]);
                }
            }
            #pragma unroll
            for (int jj = 0; jj < 2; ++jj) {
                float4 sv = make_float4(acc[jj][0] * scale, acc[jj][1] * scale,
                                        acc[jj][2] * scale, acc[jj][3] * scale);
                *(float4*)&sc[(j_thr * 2 + jj) * 64 + i_thr * 4] = sv;
            }
        }
        __syncthreads();

        // ---- softmax over columns: 8 partials per column
        const int col = tid & 63, sub = tid >> 6;
        {
            float part = -1e30f;
            #pragma unroll
            for (int jj = 0; jj < 8; ++jj)
                part = fmaxf(part, sc[(sub * 8 + jj) * 64 + col]);
            red[sub * 64 + col] = part;
        }
        __syncthreads();
        {
            float m = red[col];
            #pragma unroll
            for (int r = 1; r < 8; ++r) m = fmaxf(m, red[r * 64 + col]);
            __syncthreads();
            float s = 0.f;
            #pragma unroll
            for (int jj = 0; jj < 8; ++jj) {
                int a = (sub * 8 + jj) * 64 + col;
                float e = __expf(sc[a] - m);
                sc[a] = e; s += e;
            }
            red[sub * 64 + col] = s;
        }
        __syncthreads();
        if (tid < 64) {
            float tot = red[tid];
            #pragma unroll
            for (int r = 1; r < 8; ++r) tot += red[r * 64 + tid];
            red[tid] = __frcp_rn(tot);
        }
        __syncthreads();

        // ---- AV -> xs[t][qo..] (tf32, proj input)
        {
            const int i_thr = tid & 15, d_thr = tid >> 4;   // d 0..31
            const int i0 = i_thr * 4;
            float acc[2][4] = {};
            #pragma unroll 4
            for (int j0 = 0; j0 < 64; j0 += 4) {
                float4 va = *(const float4*)&qkvs[(vo + d_thr) * QKT + j0];
                float4 vb = *(const float4*)&qkvs[(vo + ((d_thr + 16) & 31)) * QKT + j0];
                float a4[4] = {va.x, va.y, va.z, va.w};
                float b4[4] = {vb.x, vb.y, vb.z, vb.w};
                #pragma unroll
                for (int jj = 0; jj < 4; ++jj) {
                    float4 sv = *(const float4*)&sc[(j0 + jj) * 64 + i0];
                    acc[0][0] = fmaf(a4[jj], sv.x, acc[0][0]);
                    acc[0][1] = fmaf(a4[jj], sv.y, acc[0][1]);
                    acc[0][2] = fmaf(a4[jj], sv.z, acc[0][2]);
                    acc[0][3] = fmaf(a4[jj], sv.w, acc[0][3]);
                    acc[1][0] = fmaf(b4[jj], sv.x, acc[1][0]);
                    acc[1][1] = fmaf(b4[jj], sv.y, acc[1][1]);
                    acc[1][2] = fmaf(b4[jj], sv.z, acc[1][2]);
                    acc[1][3] = fmaf(b4[jj], sv.w, acc[1][3]);
                }
            }
            float4 iv = *(const float4*)&red[i0];
            float inv[4] = {iv.x, iv.y, iv.z, iv.w};
            #pragma unroll
            for (int dd = 0; dd < 2; ++dd) {
                int c = qo + ((d_thr + 16 * dd) & 31);
                #pragma unroll
                for (int ii = 0; ii < 4; ++ii)
                    xs[(i0 + ii) * XST + c] = to_tf32(acc[dd][ii] * inv[ii]);
            }
        }
        __syncthreads();   // sc/red free for next head; xs columns committed
    }

    // ================= proj GEMM (tensor): po[o][t] into qkvs region ========
    const uint4* wpf = g_wpf;
    gemm_chunk128(wpf, 0, xs, (const float*)0, qkvs, 0,   warp, lane);
    gemm_chunk64 (wpf, 8, xs, (const float*)0, qkvs, 128, warp, lane);
    __syncthreads();

    // ================= scatter + proj bias ==================================
    #pragma unroll 4
    for (int idx = tid; idx < C_DIM * 64; idx += THREADS) {
        int c = idx >> 6, t = idx & 63;
        out[((size_t)c << 18) + goff[t]] = qkvs[c * QKT + t] + __ldg(proj_b + c);
    }
}

extern "C" void kernel_launch(void* const* d_in, const int* in_sizes, int n_in,
                              void* d_out, int out_size)
{
    const float* x      = (const float*)d_in[0];
    const float* qkv_w  = (const float*)d_in[1];
    const float* qkv_b  = (const float*)d_in[2];
    const float* proj_w = (const float*)d_in[3];
    const float* proj_b = (const float*)d_in[4];
    float* out = (float*)d_out;

    int n_prep = 36 * 24 * 32 + 12 * 24 * 32;   // 36864
    prep_frags<<<(n_prep + 255) / 256, 256>>>(qkv_w, proj_w);

    cudaFuncSetAttribute(win_attn_mma,
                         cudaFuncAttributeMaxDynamicSharedMemorySize, SMEM_BYTES);
    win_attn_mma<<<NWIN, THREADS, SMEM_BYTES>>>(x, qkv_b, proj_b, out);
}